// round 1
// baseline (speedup 1.0000x reference)
#include <cuda_runtime.h>
#include <cuda_bf16.h>
#include <stdint.h>

#define BQ   32
#define SEQ  1024
#define DIM  512
#define NTOK (BQ*SEQ)

// Scratch (device-global; no allocations allowed)
__device__ float g_x[NTOK*DIM];                       // 64 MB
__device__ float g_q[NTOK*DIM];                       // 64 MB
__device__ float g_k[NTOK*DIM];                       // 64 MB
__device__ float g_v[NTOK*DIM];                       // 64 MB
__device__ float g_s[(size_t)BQ*SEQ*SEQ];             // 128 MB (scores / attn)

// ---------------------------------------------------------------------------
// Kernel 1: embedding gather + LayerNorm  ->  g_x [NTOK, DIM]
// One block per token, 128 threads, 4 floats (one float4) per thread.
// ---------------------------------------------------------------------------
__global__ void embed_ln_kernel(const int* __restrict__ inp,
                                const float* __restrict__ wemb,
                                const float* __restrict__ pemb,
                                const float* __restrict__ gamma,
                                const float* __restrict__ beta)
{
    const int tok = blockIdx.x;
    const int s   = tok & (SEQ - 1);
    const int tid = threadIdx.x;                     // 0..127
    const int id  = inp[tok];

    const float4 w = ((const float4*)(wemb + (long long)id * DIM))[tid];
    const float4 p = ((const float4*)(pemb + (long long)s  * DIM))[tid];
    float4 e;
    e.x = w.x + p.x; e.y = w.y + p.y; e.z = w.z + p.z; e.w = w.w + p.w;

    float sum = e.x + e.y + e.z + e.w;
    float sq  = e.x*e.x + e.y*e.y + e.z*e.z + e.w*e.w;

    __shared__ float sS[4], sQ[4];
    #pragma unroll
    for (int o = 16; o > 0; o >>= 1) {
        sum += __shfl_xor_sync(0xFFFFFFFFu, sum, o);
        sq  += __shfl_xor_sync(0xFFFFFFFFu, sq,  o);
    }
    if ((tid & 31) == 0) { sS[tid >> 5] = sum; sQ[tid >> 5] = sq; }
    __syncthreads();
    sum = sS[0] + sS[1] + sS[2] + sS[3];
    sq  = sQ[0] + sQ[1] + sQ[2] + sQ[3];

    const float mean = sum * (1.0f / DIM);
    const float var  = sq  * (1.0f / DIM) - mean * mean;
    const float inv  = rsqrtf(var + 1e-5f);

    const float4 ga = ((const float4*)gamma)[tid];
    const float4 be = ((const float4*)beta)[tid];
    float4 o;
    o.x = (e.x - mean) * inv * ga.x + be.x;
    o.y = (e.y - mean) * inv * ga.y + be.y;
    o.z = (e.z - mean) * inv * ga.z + be.z;
    o.w = (e.w - mean) * inv * ga.w + be.w;
    ((float4*)(g_x + (long long)tok * DIM))[tid] = o;
}

// ---------------------------------------------------------------------------
// Generic batched GEMM with bf16 2-term split (3 MMAs): near-fp32 accuracy.
//   C[M,N] = A[M,K] (row-major) * Beff[K,N]
// BMODE 0: B stored row-major [K, N]   (projections: W; AV: V)
// BMODE 1: B stored row-major [N, K]   (QK^T: B = K-matrix)
// Block tile 128x128x32, 256 threads (8 warps, 2x4), warp tile 64x32.
// mma.sync.aligned.m16n8k16.row.col.f32.bf16.bf16.f32
// ---------------------------------------------------------------------------
__device__ __forceinline__ void mma16816(float* d, const uint32_t* a, const uint32_t* b)
{
    asm volatile(
        "mma.sync.aligned.m16n8k16.row.col.f32.bf16.bf16.f32 "
        "{%0,%1,%2,%3},{%4,%5,%6,%7},{%8,%9},{%0,%1,%2,%3};\n"
        : "+f"(d[0]), "+f"(d[1]), "+f"(d[2]), "+f"(d[3])
        : "r"(a[0]), "r"(a[1]), "r"(a[2]), "r"(a[3]), "r"(b[0]), "r"(b[1]));
}

__device__ __forceinline__ void split2(float x, __nv_bfloat16& h, __nv_bfloat16& l)
{
    h = __float2bfloat16(x);
    l = __float2bfloat16(x - __bfloat162float(h));
}

template <int BMODE>
__global__ void __launch_bounds__(256, 1)
gemm_bf16x3(const float* __restrict__ Ag, const float* __restrict__ Bg,
            float* __restrict__ Cg, int K, int lda, int ldb, int ldc,
            long long sA, long long sB, long long sC)
{
    constexpr int BM = 128, BN = 128, BK = 32, BKP = 40;  // pad -> conflict-free frags
    __shared__ __nv_bfloat16 Ah[BM][BKP], Al[BM][BKP];
    __shared__ __nv_bfloat16 Bh[BN][BKP], Bl[BN][BKP];

    const int tid = threadIdx.x;
    const int z   = blockIdx.z;
    const float* A = Ag + (long long)z * sA + (long long)blockIdx.y * BM * lda;
    const float* B;
    if (BMODE == 0) B = Bg + (long long)z * sB + blockIdx.x * BN;
    else            B = Bg + (long long)z * sB + (long long)blockIdx.x * BN * ldb;
    float* C = Cg + (long long)z * sC + (long long)blockIdx.y * BM * ldc + blockIdx.x * BN;

    const int warp = tid >> 5, lane = tid & 31;
    const int wm = (warp >> 2) * 64;   // 2 warps along M
    const int wn = (warp & 3) * 32;    // 4 warps along N

    float acc[4][4][4];
    #pragma unroll
    for (int i = 0; i < 4; i++)
        #pragma unroll
        for (int j = 0; j < 4; j++)
            #pragma unroll
            for (int c = 0; c < 4; c++) acc[i][j][c] = 0.0f;

    const int ar  = tid >> 3;          // 0..31 (+32*i rows)
    const int ac  = (tid & 7) * 4;     // 0..28 (float4 col)
    const int bkr = tid >> 5;          // mode0: k row 0..7 (+8*i)
    const int bnc = (tid & 31) * 4;    // mode0: n col

    for (int kt = 0; kt < K; kt += BK) {
        // --- load A tile (hi/lo) ---
        #pragma unroll
        for (int i = 0; i < 4; i++) {
            const int r = ar + 32 * i;
            float4 v = *(const float4*)(A + (long long)r * lda + kt + ac);
            __nv_bfloat16 h0, h1, h2, h3, l0, l1, l2, l3;
            split2(v.x, h0, l0); split2(v.y, h1, l1);
            split2(v.z, h2, l2); split2(v.w, h3, l3);
            *(__nv_bfloat162*)&Ah[r][ac]     = __nv_bfloat162(h0, h1);
            *(__nv_bfloat162*)&Ah[r][ac + 2] = __nv_bfloat162(h2, h3);
            *(__nv_bfloat162*)&Al[r][ac]     = __nv_bfloat162(l0, l1);
            *(__nv_bfloat162*)&Al[r][ac + 2] = __nv_bfloat162(l2, l3);
        }
        // --- load B tile (hi/lo), stored as [n][k] in smem ---
        if (BMODE == 1) {
            #pragma unroll
            for (int i = 0; i < 4; i++) {
                const int n = ar + 32 * i;
                float4 v = *(const float4*)(B + (long long)n * ldb + kt + ac);
                __nv_bfloat16 h0, h1, h2, h3, l0, l1, l2, l3;
                split2(v.x, h0, l0); split2(v.y, h1, l1);
                split2(v.z, h2, l2); split2(v.w, h3, l3);
                *(__nv_bfloat162*)&Bh[n][ac]     = __nv_bfloat162(h0, h1);
                *(__nv_bfloat162*)&Bh[n][ac + 2] = __nv_bfloat162(h2, h3);
                *(__nv_bfloat162*)&Bl[n][ac]     = __nv_bfloat162(l0, l1);
                *(__nv_bfloat162*)&Bl[n][ac + 2] = __nv_bfloat162(l2, l3);
            }
        } else {
            #pragma unroll
            for (int i = 0; i < 4; i++) {
                const int k = bkr + 8 * i;
                float4 v = *(const float4*)(B + (long long)(kt + k) * ldb + bnc);
                float vv[4] = {v.x, v.y, v.z, v.w};
                #pragma unroll
                for (int j = 0; j < 4; j++) {
                    __nv_bfloat16 h, l;
                    split2(vv[j], h, l);
                    Bh[bnc + j][k] = h;
                    Bl[bnc + j][k] = l;
                }
            }
        }
        __syncthreads();

        #pragma unroll
        for (int ks = 0; ks < 2; ks++) {
            const int k0 = ks * 16;
            const int r  = lane >> 2;
            const int c2 = (lane & 3) * 2;
            uint32_t aH[4][4], aL[4][4], bH[4][2], bL[4][2];
            #pragma unroll
            for (int mt = 0; mt < 4; mt++) {
                const int m = wm + mt * 16 + r;
                aH[mt][0] = *(const uint32_t*)&Ah[m][k0 + c2];
                aH[mt][1] = *(const uint32_t*)&Ah[m + 8][k0 + c2];
                aH[mt][2] = *(const uint32_t*)&Ah[m][k0 + c2 + 8];
                aH[mt][3] = *(const uint32_t*)&Ah[m + 8][k0 + c2 + 8];
                aL[mt][0] = *(const uint32_t*)&Al[m][k0 + c2];
                aL[mt][1] = *(const uint32_t*)&Al[m + 8][k0 + c2];
                aL[mt][2] = *(const uint32_t*)&Al[m][k0 + c2 + 8];
                aL[mt][3] = *(const uint32_t*)&Al[m + 8][k0 + c2 + 8];
            }
            #pragma unroll
            for (int nt = 0; nt < 4; nt++) {
                const int n = wn + nt * 8 + r;
                bH[nt][0] = *(const uint32_t*)&Bh[n][k0 + c2];
                bH[nt][1] = *(const uint32_t*)&Bh[n][k0 + c2 + 8];
                bL[nt][0] = *(const uint32_t*)&Bl[n][k0 + c2];
                bL[nt][1] = *(const uint32_t*)&Bl[n][k0 + c2 + 8];
            }
            #pragma unroll
            for (int mt = 0; mt < 4; mt++)
                #pragma unroll
                for (int nt = 0; nt < 4; nt++) {
                    mma16816(acc[mt][nt], aH[mt], bH[nt]);  // hi*hi
                    mma16816(acc[mt][nt], aH[mt], bL[nt]);  // hi*lo
                    mma16816(acc[mt][nt], aL[mt], bH[nt]);  // lo*hi
                }
        }
        __syncthreads();
    }

    // epilogue
    const int r  = lane >> 2;
    const int c2 = (lane & 3) * 2;
    #pragma unroll
    for (int mt = 0; mt < 4; mt++)
        #pragma unroll
        for (int nt = 0; nt < 4; nt++) {
            const long long row = wm + mt * 16 + r;
            const int col = wn + nt * 8 + c2;
            *(float2*)&C[row * ldc + col]       = make_float2(acc[mt][nt][0], acc[mt][nt][1]);
            *(float2*)&C[(row + 8) * ldc + col] = make_float2(acc[mt][nt][2], acc[mt][nt][3]);
        }
}

// ---------------------------------------------------------------------------
// Kernel 3: row softmax over scores (scale 1/sqrt(512) folded in).
// One block (256 thr) per row of 1024 floats.
// ---------------------------------------------------------------------------
__global__ void softmax_kernel(float* __restrict__ S)
{
    const long long row = (long long)blockIdx.y * SEQ + blockIdx.x;
    float4* p = (float4*)(S + row * SEQ);
    const int tid = threadIdx.x;                 // 0..255
    const int warp = tid >> 5, lane = tid & 31;

    const float scale = 0.044194173824159216f;   // 1/sqrt(512)
    float4 v = p[tid];
    v.x *= scale; v.y *= scale; v.z *= scale; v.w *= scale;

    __shared__ float redM[8], redS[8];

    float mx = fmaxf(fmaxf(v.x, v.y), fmaxf(v.z, v.w));
    #pragma unroll
    for (int o = 16; o > 0; o >>= 1) mx = fmaxf(mx, __shfl_xor_sync(0xFFFFFFFFu, mx, o));
    if (lane == 0) redM[warp] = mx;
    __syncthreads();
    mx = redM[0];
    #pragma unroll
    for (int i = 1; i < 8; i++) mx = fmaxf(mx, redM[i]);

    float e0 = expf(v.x - mx), e1 = expf(v.y - mx);
    float e2 = expf(v.z - mx), e3 = expf(v.w - mx);
    float sum = e0 + e1 + e2 + e3;
    #pragma unroll
    for (int o = 16; o > 0; o >>= 1) sum += __shfl_xor_sync(0xFFFFFFFFu, sum, o);
    if (lane == 0) redS[warp] = sum;
    __syncthreads();
    sum = redS[0] + redS[1] + redS[2] + redS[3] + redS[4] + redS[5] + redS[6] + redS[7];

    const float inv = 1.0f / sum;
    p[tid] = make_float4(e0 * inv, e1 * inv, e2 * inv, e3 * inv);
}

// ---------------------------------------------------------------------------
extern "C" void kernel_launch(void* const* d_in, const int* in_sizes, int n_in,
                              void* d_out, int out_size)
{
    const int*   inp   = (const int*)  d_in[0];
    const float* wemb  = (const float*)d_in[1];
    const float* pemb  = (const float*)d_in[2];
    const float* gamma = (const float*)d_in[3];
    const float* beta  = (const float*)d_in[4];
    const float* Wk    = (const float*)d_in[5];
    const float* Wq    = (const float*)d_in[6];
    const float* Wv    = (const float*)d_in[7];
    float* out = (float*)d_out;

    float *px, *pq, *pk, *pv, *ps;
    cudaGetSymbolAddress((void**)&px, g_x);
    cudaGetSymbolAddress((void**)&pq, g_q);
    cudaGetSymbolAddress((void**)&pk, g_k);
    cudaGetSymbolAddress((void**)&pv, g_v);
    cudaGetSymbolAddress((void**)&ps, g_s);

    // 1) embedding + layernorm
    embed_ln_kernel<<<NTOK, 128>>>(inp, wemb, pemb, gamma, beta);

    // 2) Q/K/V projections: [32768,512] x [512,512]
    dim3 gproj(DIM / 128, NTOK / 128, 1);
    gemm_bf16x3<0><<<gproj, 256>>>(px, Wq, pq, DIM, DIM, DIM, DIM, 0, 0, 0);
    gemm_bf16x3<0><<<gproj, 256>>>(px, Wk, pk, DIM, DIM, DIM, DIM, 0, 0, 0);
    gemm_bf16x3<0><<<gproj, 256>>>(px, Wv, pv, DIM, DIM, DIM, DIM, 0, 0, 0);

    // 3) scores = Q @ K^T  (batched over 32)
    dim3 gsc(SEQ / 128, SEQ / 128, BQ);
    gemm_bf16x3<1><<<gsc, 256>>>(pq, pk, ps, DIM, DIM, DIM, SEQ,
                                 (long long)SEQ * DIM, (long long)SEQ * DIM,
                                 (long long)SEQ * SEQ);

    // 4) softmax rows (with 1/sqrt(512))
    softmax_kernel<<<dim3(SEQ, BQ), 256>>>(ps);

    // 5) out = attn @ V  (batched over 32)
    dim3 gav(DIM / 128, SEQ / 128, BQ);
    gemm_bf16x3<0><<<gav, 256>>>(ps, pv, out, SEQ, SEQ, DIM, DIM,
                                 (long long)SEQ * SEQ, (long long)SEQ * DIM,
                                 (long long)SEQ * DIM);
}

// round 2
// speedup vs baseline: 2.3606x; 2.3606x over previous
#include <cuda_runtime.h>
#include <cuda_bf16.h>
#include <stdint.h>

#define BQ   32
#define SEQ  1024
#define DIM  512
#define NTOK (BQ*SEQ)
typedef __nv_bfloat16 bf16;

// ---------------- scratch (device globals; no allocs allowed) ----------------
__device__ bf16 g_xh[NTOK*DIM], g_xl[NTOK*DIM];
__device__ bf16 g_qh[NTOK*DIM], g_ql[NTOK*DIM];
__device__ bf16 g_kh[NTOK*DIM], g_kl[NTOK*DIM];
__device__ bf16 g_vh[NTOK*DIM], g_vl[NTOK*DIM];
__device__ bf16 g_ah[(size_t)BQ*SEQ*SEQ], g_al[(size_t)BQ*SEQ*SEQ];
__device__ float g_s[(size_t)BQ*SEQ*SEQ];
__device__ bf16 g_wh[3*DIM*DIM], g_wl[3*DIM*DIM];

__device__ __forceinline__ void split2(float x, bf16& h, bf16& l)
{
    h = __float2bfloat16(x);
    l = __float2bfloat16(x - __bfloat162float(h));
}

// ---------------- PTX helpers ----------------
__device__ __forceinline__ uint32_t smem_u32(const void* p){
    return (uint32_t)__cvta_generic_to_shared(p);
}
__device__ __forceinline__ void cp16(uint32_t s, const void* g){
    asm volatile("cp.async.cg.shared.global [%0],[%1],16;\n" :: "r"(s), "l"(g));
}
__device__ __forceinline__ void cp_commit(){ asm volatile("cp.async.commit_group;\n" ::: "memory"); }
template<int N> __device__ __forceinline__ void cp_wait(){
    asm volatile("cp.async.wait_group %0;\n" :: "n"(N) : "memory");
}
__device__ __forceinline__ void ldsm4(uint32_t* r, uint32_t a){
    asm volatile("ldmatrix.sync.aligned.m8n8.x4.shared.b16 {%0,%1,%2,%3},[%4];\n"
        : "=r"(r[0]),"=r"(r[1]),"=r"(r[2]),"=r"(r[3]) : "r"(a));
}
__device__ __forceinline__ void ldsm4t(uint32_t* r, uint32_t a){
    asm volatile("ldmatrix.sync.aligned.m8n8.x4.trans.shared.b16 {%0,%1,%2,%3},[%4];\n"
        : "=r"(r[0]),"=r"(r[1]),"=r"(r[2]),"=r"(r[3]) : "r"(a));
}
__device__ __forceinline__ void mma16816(float* d, const uint32_t* a, const uint32_t* b)
{
    asm volatile(
        "mma.sync.aligned.m16n8k16.row.col.f32.bf16.bf16.f32 "
        "{%0,%1,%2,%3},{%4,%5,%6,%7},{%8,%9},{%0,%1,%2,%3};\n"
        : "+f"(d[0]), "+f"(d[1]), "+f"(d[2]), "+f"(d[3])
        : "r"(a[0]), "r"(a[1]), "r"(a[2]), "r"(a[3]), "r"(b[0]), "r"(b[1]));
}

// ---------------- kernel: split weights into bf16 hi/lo ----------------
__global__ void split_w_kernel(const float* __restrict__ wq,
                               const float* __restrict__ wk,
                               const float* __restrict__ wv)
{
    const int i = blockIdx.x * blockDim.x + threadIdx.x;   // 0 .. 3*DIM*DIM-1
    const int slot = i / (DIM*DIM);
    const int off  = i - slot * (DIM*DIM);
    const float* src = (slot == 0) ? wq : (slot == 1) ? wk : wv;
    bf16 h, l;
    split2(src[off], h, l);
    g_wh[i] = h; g_wl[i] = l;
}

// ---------------- kernel: embedding + LayerNorm -> xh/xl ----------------
__global__ void embed_ln_kernel(const int* __restrict__ inp,
                                const float* __restrict__ wemb,
                                const float* __restrict__ pemb,
                                const float* __restrict__ gamma,
                                const float* __restrict__ beta)
{
    const int tok = blockIdx.x;
    const int s   = tok & (SEQ - 1);
    const int tid = threadIdx.x;                     // 0..127
    const int id  = inp[tok];

    const float4 w = ((const float4*)(wemb + (long long)id * DIM))[tid];
    const float4 p = ((const float4*)(pemb + (long long)s  * DIM))[tid];
    float4 e;
    e.x = w.x + p.x; e.y = w.y + p.y; e.z = w.z + p.z; e.w = w.w + p.w;

    float sum = e.x + e.y + e.z + e.w;
    float sq  = e.x*e.x + e.y*e.y + e.z*e.z + e.w*e.w;

    __shared__ float sS[4], sQ[4];
    #pragma unroll
    for (int o = 16; o > 0; o >>= 1) {
        sum += __shfl_xor_sync(0xFFFFFFFFu, sum, o);
        sq  += __shfl_xor_sync(0xFFFFFFFFu, sq,  o);
    }
    if ((tid & 31) == 0) { sS[tid >> 5] = sum; sQ[tid >> 5] = sq; }
    __syncthreads();
    sum = sS[0] + sS[1] + sS[2] + sS[3];
    sq  = sQ[0] + sQ[1] + sQ[2] + sQ[3];

    const float mean = sum * (1.0f / DIM);
    const float var  = sq  * (1.0f / DIM) - mean * mean;
    const float inv  = rsqrtf(var + 1e-5f);

    const float4 ga = ((const float4*)gamma)[tid];
    const float4 be = ((const float4*)beta)[tid];
    float o0 = (e.x - mean) * inv * ga.x + be.x;
    float o1 = (e.y - mean) * inv * ga.y + be.y;
    float o2 = (e.z - mean) * inv * ga.z + be.z;
    float o3 = (e.w - mean) * inv * ga.w + be.w;

    bf16 h0,h1,h2,h3,l0,l1,l2,l3;
    split2(o0,h0,l0); split2(o1,h1,l1); split2(o2,h2,l2); split2(o3,h3,l3);
    const long long base = (long long)tok * DIM + tid * 4;
    *(__nv_bfloat162*)&g_xh[base]   = __nv_bfloat162(h0,h1);
    *(__nv_bfloat162*)&g_xh[base+2] = __nv_bfloat162(h2,h3);
    *(__nv_bfloat162*)&g_xl[base]   = __nv_bfloat162(l0,l1);
    *(__nv_bfloat162*)&g_xl[base+2] = __nv_bfloat162(l2,l3);
}

// ---------------------------------------------------------------------------
// GEMM: C[M,N] = A[M,K] * B, all operands pre-split bf16 hi/lo.
//   BKN=0 : B global layout [N][K] (k contiguous)  -> ldmatrix non-trans
//   BKN=1 : B global layout [K][N] (n contiguous)  -> ldmatrix trans
//   OSPLIT=1 : write C as bf16 hi/lo pair; OSPLIT=0 : write fp32
// 128x128x32 tiles, 256 thr (8 warps 2x4, warp tile 64x32), 3-stage cp.async,
// conflict-free smem (pitch-40 rows for K-major, XOR swizzle for N-major).
// ---------------------------------------------------------------------------
template<int BKN, int OSPLIT>
__global__ void __launch_bounds__(256, 1)
gemm2(const bf16* __restrict__ Ah_g, const bf16* __restrict__ Al_g,
      const bf16* __restrict__ Bh_g, const bf16* __restrict__ Bl_g,
      float* __restrict__ Cf, bf16* __restrict__ Ch, bf16* __restrict__ Cl,
      int K, int lda, int ldb, int ldc,
      long long sA, long long sB, long long sC)
{
    constexpr int BM = 128, BN = 128, BK = 32, S = 3, AP = 40;
    constexpr int ASZ   = BM * AP * 2;      // 10240 B per A matrix
    constexpr int BSLOT = 10240;            // max(B_NK=10240, B_KN=8192)
    constexpr int STAGE = 2*ASZ + 2*BSLOT;  // 40960 B

    extern __shared__ char smem[];
    const uint32_t sbase = smem_u32(smem);

    const int tid  = threadIdx.x;
    const int warp = tid >> 5, lane = tid & 31;
    const int z    = blockIdx.z;

    const bf16* Ah = Ah_g + z * sA + (long long)blockIdx.y * BM * lda;
    const bf16* Al = Al_g + z * sA + (long long)blockIdx.y * BM * lda;
    const bf16* Bh; const bf16* Bl;
    if (BKN == 0) { Bh = Bh_g + z*sB + (long long)blockIdx.x * BN * ldb;
                    Bl = Bl_g + z*sB + (long long)blockIdx.x * BN * ldb; }
    else          { Bh = Bh_g + z*sB + blockIdx.x * BN;
                    Bl = Bl_g + z*sB + blockIdx.x * BN; }

    const int wm = (warp >> 2) * 64;
    const int wn = (warp & 3) * 32;

    float acc[4][4][4];
    #pragma unroll
    for (int i = 0; i < 4; i++)
        #pragma unroll
        for (int j = 0; j < 4; j++)
            #pragma unroll
            for (int c = 0; c < 4; c++) acc[i][j][c] = 0.0f;

    // ---- async tile loader ----
    auto load_tile = [&](int s, int kt) {
        const uint32_t aOff  = sbase + s * STAGE;
        const uint32_t alOff = aOff + ASZ;
        const uint32_t bOff  = aOff + 2*ASZ;
        const uint32_t blOff = bOff + BSLOT;
        // A: 128 rows x 4 chunks(16B); 2 chunks/thread
        {
            const int r  = tid >> 1;
            const int cb = (tid & 1) * 2;
            #pragma unroll
            for (int j = 0; j < 2; j++) {
                const int c = cb + j;
                const long long go = (long long)r * lda + kt + c * 8;
                const uint32_t so = (uint32_t)(r * AP + c * 8) * 2;
                cp16(aOff  + so, Ah + go);
                cp16(alOff + so, Al + go);
            }
        }
        if (BKN == 0) {
            const int r  = tid >> 1;
            const int cb = (tid & 1) * 2;
            #pragma unroll
            for (int j = 0; j < 2; j++) {
                const int c = cb + j;
                const long long go = (long long)r * ldb + kt + c * 8;
                const uint32_t so = (uint32_t)(r * AP + c * 8) * 2;
                cp16(bOff  + so, Bh + go);
                cp16(blOff + so, Bl + go);
            }
        } else {
            const int k  = tid >> 3;              // 0..31
            const int cb = (tid & 7) * 2;         // chunk base 0..14
            #pragma unroll
            for (int j = 0; j < 2; j++) {
                const int c = cb + j;
                const long long go = (long long)(kt + k) * ldb + c * 8;
                const uint32_t so = (uint32_t)(k * 256 + ((c ^ (k & 7)) * 16));
                cp16(bOff  + so, Bh + go);
                cp16(blOff + so, Bl + go);
            }
        }
    };

    // ---- compute one K-tile from stage s ----
    auto compute_tile = [&](int s) {
        const uint32_t aB  = sbase + s * STAGE;
        const uint32_t alB = aB + ASZ;
        const uint32_t bB  = aB + 2*ASZ;
        const uint32_t blB = bB + BSLOT;
        const int g = lane >> 3, idx = lane & 7;
        #pragma unroll
        for (int ks = 0; ks < 2; ks++) {
            const int k0 = ks * 16;
            uint32_t aH[4][4], aL[4][4], bH[4][2], bL[4][2];
            {   // A fragments
                const int arow = wm + (g & 1) * 8 + idx;
                const int acol = k0 + (g >> 1) * 8;
                #pragma unroll
                for (int mt = 0; mt < 4; mt++) {
                    const uint32_t so = (uint32_t)((arow + mt*16) * AP + acol) * 2;
                    ldsm4(aH[mt], aB  + so);
                    ldsm4(aL[mt], alB + so);
                }
            }
            if (BKN == 0) {
                const int brow = wn + (g >> 1) * 8 + idx;
                const int bcol = k0 + (g & 1) * 8;
                #pragma unroll
                for (int p = 0; p < 2; p++) {
                    const uint32_t so = (uint32_t)((brow + p*16) * AP + bcol) * 2;
                    uint32_t r[4];
                    ldsm4(r, bB + so);
                    bH[2*p][0]=r[0]; bH[2*p][1]=r[1]; bH[2*p+1][0]=r[2]; bH[2*p+1][1]=r[3];
                    ldsm4(r, blB + so);
                    bL[2*p][0]=r[0]; bL[2*p][1]=r[1]; bL[2*p+1][0]=r[2]; bL[2*p+1][1]=r[3];
                }
            } else {
                const int krow = k0 + (g & 1) * 8 + idx;
                #pragma unroll
                for (int p = 0; p < 2; p++) {
                    const int nch = (wn + p*16 + (g >> 1) * 8) >> 3;
                    const uint32_t so = (uint32_t)(krow * 256 + ((nch ^ (krow & 7)) * 16));
                    uint32_t r[4];
                    ldsm4t(r, bB + so);
                    bH[2*p][0]=r[0]; bH[2*p][1]=r[1]; bH[2*p+1][0]=r[2]; bH[2*p+1][1]=r[3];
                    ldsm4t(r, blB + so);
                    bL[2*p][0]=r[0]; bL[2*p][1]=r[1]; bL[2*p+1][0]=r[2]; bL[2*p+1][1]=r[3];
                }
            }
            // three passes: hh, hl, lh (no back-to-back acc deps)
            #pragma unroll
            for (int mt = 0; mt < 4; mt++)
                #pragma unroll
                for (int nt = 0; nt < 4; nt++) mma16816(acc[mt][nt], aH[mt], bH[nt]);
            #pragma unroll
            for (int mt = 0; mt < 4; mt++)
                #pragma unroll
                for (int nt = 0; nt < 4; nt++) mma16816(acc[mt][nt], aH[mt], bL[nt]);
            #pragma unroll
            for (int mt = 0; mt < 4; mt++)
                #pragma unroll
                for (int nt = 0; nt < 4; nt++) mma16816(acc[mt][nt], aL[mt], bH[nt]);
        }
    };

    const int T = K / BK;
    // prologue: fill S-1 stages
    #pragma unroll
    for (int s = 0; s < S - 1; s++) { load_tile(s, s * BK); cp_commit(); }

    for (int t = 0; t < T; t++) {
        cp_wait<S - 2>();
        __syncthreads();
        compute_tile(t % S);
        const int tn = t + S - 1;
        if (tn < T) load_tile(tn % S, tn * BK);
        cp_commit();
    }

    // ---- epilogue ----
    const int r  = lane >> 2;
    const int c2 = (lane & 3) * 2;
    if (OSPLIT == 0) {
        float* C = Cf + z * sC + (long long)blockIdx.y * BM * ldc + blockIdx.x * BN;
        #pragma unroll
        for (int mt = 0; mt < 4; mt++)
            #pragma unroll
            for (int nt = 0; nt < 4; nt++) {
                const long long row = wm + mt * 16 + r;
                const int col = wn + nt * 8 + c2;
                *(float2*)&C[row * ldc + col]       = make_float2(acc[mt][nt][0], acc[mt][nt][1]);
                *(float2*)&C[(row + 8) * ldc + col] = make_float2(acc[mt][nt][2], acc[mt][nt][3]);
            }
    } else {
        bf16* CH = Ch + z * sC + (long long)blockIdx.y * BM * ldc + blockIdx.x * BN;
        bf16* CL = Cl + z * sC + (long long)blockIdx.y * BM * ldc + blockIdx.x * BN;
        #pragma unroll
        for (int mt = 0; mt < 4; mt++)
            #pragma unroll
            for (int nt = 0; nt < 4; nt++) {
                const long long row = wm + mt * 16 + r;
                const int col = wn + nt * 8 + c2;
                bf16 h0,h1,l0,l1;
                split2(acc[mt][nt][0], h0, l0); split2(acc[mt][nt][1], h1, l1);
                *(__nv_bfloat162*)&CH[row * ldc + col] = __nv_bfloat162(h0,h1);
                *(__nv_bfloat162*)&CL[row * ldc + col] = __nv_bfloat162(l0,l1);
                split2(acc[mt][nt][2], h0, l0); split2(acc[mt][nt][3], h1, l1);
                *(__nv_bfloat162*)&CH[(row+8) * ldc + col] = __nv_bfloat162(h0,h1);
                *(__nv_bfloat162*)&CL[(row+8) * ldc + col] = __nv_bfloat162(l0,l1);
            }
    }
}

// ---------------- kernel: softmax -> attn hi/lo ----------------
__global__ void softmax_kernel(const float* __restrict__ Sc)
{
    const long long row = (long long)blockIdx.y * SEQ + blockIdx.x;
    const float4* p = (const float4*)(Sc + row * SEQ);
    const int tid = threadIdx.x;                 // 0..255
    const int warp = tid >> 5, lane = tid & 31;

    const float scale = 0.044194173824159216f;   // 1/sqrt(512)
    float4 v = p[tid];
    v.x *= scale; v.y *= scale; v.z *= scale; v.w *= scale;

    __shared__ float redM[8], redS[8];

    float mx = fmaxf(fmaxf(v.x, v.y), fmaxf(v.z, v.w));
    #pragma unroll
    for (int o = 16; o > 0; o >>= 1) mx = fmaxf(mx, __shfl_xor_sync(0xFFFFFFFFu, mx, o));
    if (lane == 0) redM[warp] = mx;
    __syncthreads();
    mx = redM[0];
    #pragma unroll
    for (int i = 1; i < 8; i++) mx = fmaxf(mx, redM[i]);

    float e0 = expf(v.x - mx), e1 = expf(v.y - mx);
    float e2 = expf(v.z - mx), e3 = expf(v.w - mx);
    float sum = e0 + e1 + e2 + e3;
    #pragma unroll
    for (int o = 16; o > 0; o >>= 1) sum += __shfl_xor_sync(0xFFFFFFFFu, sum, o);
    if (lane == 0) redS[warp] = sum;
    __syncthreads();
    sum = redS[0]+redS[1]+redS[2]+redS[3]+redS[4]+redS[5]+redS[6]+redS[7];

    const float inv = 1.0f / sum;
    e0 *= inv; e1 *= inv; e2 *= inv; e3 *= inv;

    bf16 h0,h1,h2,h3,l0,l1,l2,l3;
    split2(e0,h0,l0); split2(e1,h1,l1); split2(e2,h2,l2); split2(e3,h3,l3);
    const long long base = row * SEQ + tid * 4;
    *(__nv_bfloat162*)&g_ah[base]   = __nv_bfloat162(h0,h1);
    *(__nv_bfloat162*)&g_ah[base+2] = __nv_bfloat162(h2,h3);
    *(__nv_bfloat162*)&g_al[base]   = __nv_bfloat162(l0,l1);
    *(__nv_bfloat162*)&g_al[base+2] = __nv_bfloat162(l2,l3);
}

// ---------------------------------------------------------------------------
extern "C" void kernel_launch(void* const* d_in, const int* in_sizes, int n_in,
                              void* d_out, int out_size)
{
    const int*   inp   = (const int*)  d_in[0];
    const float* wemb  = (const float*)d_in[1];
    const float* pemb  = (const float*)d_in[2];
    const float* gamma = (const float*)d_in[3];
    const float* beta  = (const float*)d_in[4];
    const float* Wk    = (const float*)d_in[5];
    const float* Wq    = (const float*)d_in[6];
    const float* Wv    = (const float*)d_in[7];
    float* out = (float*)d_out;

    bf16 *xh,*xl,*qh,*ql,*kh,*kl,*vh,*vl,*ah,*al,*wh,*wl;
    float *ps;
    cudaGetSymbolAddress((void**)&xh, g_xh); cudaGetSymbolAddress((void**)&xl, g_xl);
    cudaGetSymbolAddress((void**)&qh, g_qh); cudaGetSymbolAddress((void**)&ql, g_ql);
    cudaGetSymbolAddress((void**)&kh, g_kh); cudaGetSymbolAddress((void**)&kl, g_kl);
    cudaGetSymbolAddress((void**)&vh, g_vh); cudaGetSymbolAddress((void**)&vl, g_vl);
    cudaGetSymbolAddress((void**)&ah, g_ah); cudaGetSymbolAddress((void**)&al, g_al);
    cudaGetSymbolAddress((void**)&wh, g_wh); cudaGetSymbolAddress((void**)&wl, g_wl);
    cudaGetSymbolAddress((void**)&ps, g_s);

    const int SMEMSZ = 3 * 40960;  // 122880 B
    cudaFuncSetAttribute(gemm2<1,1>, cudaFuncAttributeMaxDynamicSharedMemorySize, SMEMSZ);
    cudaFuncSetAttribute(gemm2<0,0>, cudaFuncAttributeMaxDynamicSharedMemorySize, SMEMSZ);
    cudaFuncSetAttribute(gemm2<1,0>, cudaFuncAttributeMaxDynamicSharedMemorySize, SMEMSZ);

    // 0) split weights (slot order: q, k, v)
    split_w_kernel<<<3*DIM*DIM/256, 256>>>(Wq, Wk, Wv);

    // 1) embedding + layernorm -> xh/xl
    embed_ln_kernel<<<NTOK, 128>>>(inp, wemb, pemb, gamma, beta);

    // 2) Q/K/V projections: [32768,512] x W[512,512] (KN layout), split output
    dim3 gproj(DIM/128, NTOK/128, 1);
    gemm2<1,1><<<gproj, 256, SMEMSZ>>>(xh, xl, wh,             wl,             nullptr, qh, ql,
                                       DIM, DIM, DIM, DIM, 0, 0, 0);
    gemm2<1,1><<<gproj, 256, SMEMSZ>>>(xh, xl, wh + DIM*DIM,   wl + DIM*DIM,   nullptr, kh, kl,
                                       DIM, DIM, DIM, DIM, 0, 0, 0);
    gemm2<1,1><<<gproj, 256, SMEMSZ>>>(xh, xl, wh + 2*DIM*DIM, wl + 2*DIM*DIM, nullptr, vh, vl,
                                       DIM, DIM, DIM, DIM, 0, 0, 0);

    // 3) scores = Q @ K^T (batched, B = K matrix in natural [N][K] layout)
    dim3 gsc(SEQ/128, SEQ/128, BQ);
    gemm2<0,0><<<gsc, 256, SMEMSZ>>>(qh, ql, kh, kl, ps, nullptr, nullptr,
                                     DIM, DIM, DIM, SEQ,
                                     (long long)SEQ*DIM, (long long)SEQ*DIM,
                                     (long long)SEQ*SEQ);

    // 4) softmax -> attn hi/lo
    softmax_kernel<<<dim3(SEQ, BQ), 256>>>(ps);

    // 5) out = attn @ V (batched, V in natural [K][N] layout)
    dim3 gav(DIM/128, SEQ/128, BQ);
    gemm2<1,0><<<gav, 256, SMEMSZ>>>(ah, al, vh, vl, out, nullptr, nullptr,
                                     SEQ, SEQ, DIM, DIM,
                                     (long long)SEQ*SEQ, (long long)SEQ*DIM,
                                     (long long)SEQ*DIM);
}

// round 4
// speedup vs baseline: 2.6747x; 1.1331x over previous
#include <cuda_runtime.h>
#include <cuda_bf16.h>
#include <stdint.h>

#define BQ   32
#define SEQ  1024
#define DIM  512
#define NTOK (BQ*SEQ)
typedef __nv_bfloat16 bf16;

// ---------------- scratch (device globals; no allocs allowed) ----------------
__device__ bf16 g_xh[NTOK*DIM], g_xl[NTOK*DIM];
__device__ bf16 g_qh[NTOK*DIM], g_ql[NTOK*DIM];
__device__ bf16 g_kh[NTOK*DIM], g_kl[NTOK*DIM];
__device__ bf16 g_vh[NTOK*DIM], g_vl[NTOK*DIM];
__device__ bf16 g_ah[(size_t)BQ*SEQ*SEQ], g_al[(size_t)BQ*SEQ*SEQ];
__device__ float g_s[(size_t)BQ*SEQ*SEQ];
__device__ bf16 g_wh[3*DIM*DIM], g_wl[3*DIM*DIM];

__device__ __forceinline__ void split2(float x, bf16& h, bf16& l)
{
    h = __float2bfloat16(x);
    l = __float2bfloat16(x - __bfloat162float(h));
}

// ---------------- PTX helpers ----------------
__device__ __forceinline__ uint32_t smem_u32(const void* p){
    return (uint32_t)__cvta_generic_to_shared(p);
}
__device__ __forceinline__ void cp16(uint32_t s, const void* g){
    asm volatile("cp.async.cg.shared.global [%0],[%1],16;\n" :: "r"(s), "l"(g));
}
__device__ __forceinline__ void cp_commit(){ asm volatile("cp.async.commit_group;\n" ::: "memory"); }
template<int N> __device__ __forceinline__ void cp_wait(){
    asm volatile("cp.async.wait_group %0;\n" :: "n"(N) : "memory");
}
__device__ __forceinline__ void ldsm4(uint32_t* r, uint32_t a){
    asm volatile("ldmatrix.sync.aligned.m8n8.x4.shared.b16 {%0,%1,%2,%3},[%4];\n"
        : "=r"(r[0]),"=r"(r[1]),"=r"(r[2]),"=r"(r[3]) : "r"(a));
}
__device__ __forceinline__ void ldsm4t(uint32_t* r, uint32_t a){
    asm volatile("ldmatrix.sync.aligned.m8n8.x4.trans.shared.b16 {%0,%1,%2,%3},[%4];\n"
        : "=r"(r[0]),"=r"(r[1]),"=r"(r[2]),"=r"(r[3]) : "r"(a));
}
__device__ __forceinline__ void mma16816(float* d, const uint32_t* a, const uint32_t* b)
{
    asm volatile(
        "mma.sync.aligned.m16n8k16.row.col.f32.bf16.bf16.f32 "
        "{%0,%1,%2,%3},{%4,%5,%6,%7},{%8,%9},{%0,%1,%2,%3};\n"
        : "+f"(d[0]), "+f"(d[1]), "+f"(d[2]), "+f"(d[3])
        : "r"(a[0]), "r"(a[1]), "r"(a[2]), "r"(a[3]), "r"(b[0]), "r"(b[1]));
}

// K-major tile swizzle: 128 rows x 32 bf16 (64B/row). Two rows share one 128B
// line; 16B chunk cc = (r&1)*4 + c, swizzled by line&7. Conflict-free for
// cp.async writes and ldmatrix reads (8 rows -> 8 distinct bank quads).
__device__ __forceinline__ uint32_t swzA(int r, int kcol)
{
    const int line = r >> 1;
    const int cc = ((r & 1) << 2) | (kcol >> 3);
    return (uint32_t)(line * 128 + ((cc ^ (line & 7)) << 4));
}

// ---------------- kernel: split weights into bf16 hi/lo ----------------
__global__ void split_w_kernel(const float* __restrict__ wq,
                               const float* __restrict__ wk,
                               const float* __restrict__ wv)
{
    const int i = blockIdx.x * blockDim.x + threadIdx.x;   // 0 .. 3*DIM*DIM-1
    const int slot = i / (DIM*DIM);
    const int off  = i - slot * (DIM*DIM);
    const float* src = (slot == 0) ? wq : (slot == 1) ? wk : wv;
    bf16 h, l;
    split2(src[off], h, l);
    g_wh[i] = h; g_wl[i] = l;
}

// ---------------- kernel: embedding + LayerNorm -> xh/xl ----------------
__global__ void embed_ln_kernel(const int* __restrict__ inp,
                                const float* __restrict__ wemb,
                                const float* __restrict__ pemb,
                                const float* __restrict__ gamma,
                                const float* __restrict__ beta)
{
    const int tok = blockIdx.x;
    const int s   = tok & (SEQ - 1);
    const int tid = threadIdx.x;                     // 0..127
    const int id  = inp[tok];

    const float4 w = ((const float4*)(wemb + (long long)id * DIM))[tid];
    const float4 p = ((const float4*)(pemb + (long long)s  * DIM))[tid];
    float4 e;
    e.x = w.x + p.x; e.y = w.y + p.y; e.z = w.z + p.z; e.w = w.w + p.w;

    float sum = e.x + e.y + e.z + e.w;
    float sq  = e.x*e.x + e.y*e.y + e.z*e.z + e.w*e.w;

    __shared__ float sS[4], sQ[4];
    #pragma unroll
    for (int o = 16; o > 0; o >>= 1) {
        sum += __shfl_xor_sync(0xFFFFFFFFu, sum, o);
        sq  += __shfl_xor_sync(0xFFFFFFFFu, sq,  o);
    }
    if ((tid & 31) == 0) { sS[tid >> 5] = sum; sQ[tid >> 5] = sq; }
    __syncthreads();
    sum = sS[0] + sS[1] + sS[2] + sS[3];
    sq  = sQ[0] + sQ[1] + sQ[2] + sQ[3];

    const float mean = sum * (1.0f / DIM);
    const float var  = sq  * (1.0f / DIM) - mean * mean;
    const float inv  = rsqrtf(var + 1e-5f);

    const float4 ga = ((const float4*)gamma)[tid];
    const float4 be = ((const float4*)beta)[tid];
    float o0 = (e.x - mean) * inv * ga.x + be.x;
    float o1 = (e.y - mean) * inv * ga.y + be.y;
    float o2 = (e.z - mean) * inv * ga.z + be.z;
    float o3 = (e.w - mean) * inv * ga.w + be.w;

    bf16 h0,h1,h2,h3,l0,l1,l2,l3;
    split2(o0,h0,l0); split2(o1,h1,l1); split2(o2,h2,l2); split2(o3,h3,l3);
    const long long base = (long long)tok * DIM + tid * 4;
    *(__nv_bfloat162*)&g_xh[base]   = __nv_bfloat162(h0,h1);
    *(__nv_bfloat162*)&g_xh[base+2] = __nv_bfloat162(h2,h3);
    *(__nv_bfloat162*)&g_xl[base]   = __nv_bfloat162(l0,l1);
    *(__nv_bfloat162*)&g_xl[base+2] = __nv_bfloat162(l2,l3);
}

// ---------------------------------------------------------------------------
// GEMM: C[M,N] = A[M,K] * B, operands pre-split bf16 hi/lo.
//   BKN=0 : B global layout [N][K] (k contiguous)  -> ldmatrix non-trans
//   BKN=1 : B global layout [K][N] (n contiguous)  -> ldmatrix trans
//   OSPLIT=1 : write C as bf16 hi/lo pair; OSPLIT=0 : write fp32
// 128x128x32 tiles, 256 thr (8 warps 2x4, warp tile 64x32), 3-stage cp.async.
// 32KB/stage -> 96KB smem -> 2 CTAs/SM (launch_bounds 256,2).
// ---------------------------------------------------------------------------
template<int BKN, int OSPLIT>
__global__ void __launch_bounds__(256, 2)
gemm2(const bf16* __restrict__ Ah_g, const bf16* __restrict__ Al_g,
      const bf16* __restrict__ Bh_g, const bf16* __restrict__ Bl_g,
      float* __restrict__ Cf, bf16* __restrict__ Ch, bf16* __restrict__ Cl,
      int K, int lda, int ldb, int ldc,
      long long sA, long long sB, long long sC)
{
    constexpr int S = 3;
    constexpr int MATSZ = 8192;             // 128x32 bf16 (or 32x128)
    constexpr int STAGE = 4 * MATSZ;        // Ah Al Bh Bl = 32KB

    extern __shared__ char smem[];
    const uint32_t sbase = smem_u32(smem);

    const int tid  = threadIdx.x;
    const int warp = tid >> 5, lane = tid & 31;
    const int z    = blockIdx.z;

    const bf16* Ah = Ah_g + z * sA + (long long)blockIdx.y * 128 * lda;
    const bf16* Al = Al_g + z * sA + (long long)blockIdx.y * 128 * lda;
    const bf16* Bh; const bf16* Bl;
    if (BKN == 0) { Bh = Bh_g + z*sB + (long long)blockIdx.x * 128 * ldb;
                    Bl = Bl_g + z*sB + (long long)blockIdx.x * 128 * ldb; }
    else          { Bh = Bh_g + z*sB + blockIdx.x * 128;
                    Bl = Bl_g + z*sB + blockIdx.x * 128; }

    const int wm = (warp >> 2) * 64;
    const int wn = (warp & 3) * 32;

    float acc[4][4][4];
    #pragma unroll
    for (int i = 0; i < 4; i++)
        #pragma unroll
        for (int j = 0; j < 4; j++)
            #pragma unroll
            for (int c = 0; c < 4; c++) acc[i][j][c] = 0.0f;

    // ---- async tile loader ----
    auto load_tile = [&](int s, int kt) {
        const uint32_t aOff  = sbase + s * STAGE;
        const uint32_t alOff = aOff + MATSZ;
        const uint32_t bOff  = aOff + 2*MATSZ;
        const uint32_t blOff = bOff + MATSZ;
        // A: 128 rows x 4 chunks(16B) = 512 chunks; 2 per thread
        {
            const int r  = tid >> 1;
            const int cb = (tid & 1) * 2;
            #pragma unroll
            for (int j = 0; j < 2; j++) {
                const int c = cb + j;               // 16B chunk idx (8 bf16)
                const long long go = (long long)r * lda + kt + c * 8;
                const uint32_t so = swzA(r, c * 8);
                cp16(aOff  + so, Ah + go);
                cp16(alOff + so, Al + go);
            }
        }
        if (BKN == 0) {
            const int r  = tid >> 1;
            const int cb = (tid & 1) * 2;
            #pragma unroll
            for (int j = 0; j < 2; j++) {
                const int c = cb + j;
                const long long go = (long long)r * ldb + kt + c * 8;
                const uint32_t so = swzA(r, c * 8);
                cp16(bOff  + so, Bh + go);
                cp16(blOff + so, Bl + go);
            }
        } else {
            const int k  = tid >> 3;              // 0..31
            const int cb = (tid & 7) * 2;         // chunk base 0..14
            #pragma unroll
            for (int j = 0; j < 2; j++) {
                const int c = cb + j;
                const long long go = (long long)(kt + k) * ldb + c * 8;
                const uint32_t so = (uint32_t)(k * 256 + ((c ^ (k & 7)) * 16));
                cp16(bOff  + so, Bh + go);
                cp16(blOff + so, Bl + go);
            }
        }
    };

    // ---- compute one K-tile from stage s ----
    auto compute_tile = [&](int s) {
        const uint32_t aB  = sbase + s * STAGE;
        const uint32_t alB = aB + MATSZ;
        const uint32_t bB  = aB + 2*MATSZ;
        const uint32_t blB = bB + MATSZ;
        const int g = lane >> 3, idx = lane & 7;
        #pragma unroll
        for (int ks = 0; ks < 2; ks++) {
            const int k0 = ks * 16;
            uint32_t aH[4][4], aL[4][4], bH[4][2], bL[4][2];
            {   // A fragments
                const int arow = wm + (g & 1) * 8 + idx;
                const int acol = k0 + (g >> 1) * 8;
                #pragma unroll
                for (int mt = 0; mt < 4; mt++) {
                    const uint32_t so = swzA(arow + mt*16, acol);
                    ldsm4(aH[mt], aB  + so);
                    ldsm4(aL[mt], alB + so);
                }
            }
            if (BKN == 0) {
                const int brow = wn + (g >> 1) * 8 + idx;
                const int bcol = k0 + (g & 1) * 8;
                #pragma unroll
                for (int p = 0; p < 2; p++) {
                    const uint32_t so = swzA(brow + p*16, bcol);
                    uint32_t r[4];
                    ldsm4(r, bB + so);
                    bH[2*p][0]=r[0]; bH[2*p][1]=r[1]; bH[2*p+1][0]=r[2]; bH[2*p+1][1]=r[3];
                    ldsm4(r, blB + so);
                    bL[2*p][0]=r[0]; bL[2*p][1]=r[1]; bL[2*p+1][0]=r[2]; bL[2*p+1][1]=r[3];
                }
            } else {
                const int krow = k0 + (g & 1) * 8 + idx;
                #pragma unroll
                for (int p = 0; p < 2; p++) {
                    const int nch = (wn + p*16 + (g >> 1) * 8) >> 3;
                    const uint32_t so = (uint32_t)(krow * 256 + ((nch ^ (krow & 7)) * 16));
                    uint32_t r[4];
                    ldsm4t(r, bB + so);
                    bH[2*p][0]=r[0]; bH[2*p][1]=r[1]; bH[2*p+1][0]=r[2]; bH[2*p+1][1]=r[3];
                    ldsm4t(r, blB + so);
                    bL[2*p][0]=r[0]; bL[2*p][1]=r[1]; bL[2*p+1][0]=r[2]; bL[2*p+1][1]=r[3];
                }
            }
            // pass order hh, lh, hl (shortens aL/bL live ranges)
            #pragma unroll
            for (int mt = 0; mt < 4; mt++)
                #pragma unroll
                for (int nt = 0; nt < 4; nt++) mma16816(acc[mt][nt], aH[mt], bH[nt]);
            #pragma unroll
            for (int mt = 0; mt < 4; mt++)
                #pragma unroll
                for (int nt = 0; nt < 4; nt++) mma16816(acc[mt][nt], aL[mt], bH[nt]);
            #pragma unroll
            for (int mt = 0; mt < 4; mt++)
                #pragma unroll
                for (int nt = 0; nt < 4; nt++) mma16816(acc[mt][nt], aH[mt], bL[nt]);
        }
    };

    const int T = K / 32;
    #pragma unroll
    for (int s = 0; s < S - 1; s++) { load_tile(s, s * 32); cp_commit(); }

    for (int t = 0; t < T; t++) {
        cp_wait<S - 2>();
        __syncthreads();
        compute_tile(t % S);
        const int tn = t + S - 1;
        if (tn < T) load_tile(tn % S, tn * 32);
        cp_commit();
    }

    // ---- epilogue ----
    const int r  = lane >> 2;
    const int c2 = (lane & 3) * 2;
    if (OSPLIT == 0) {
        float* C = Cf + z * sC + (long long)blockIdx.y * 128 * ldc + blockIdx.x * 128;
        #pragma unroll
        for (int mt = 0; mt < 4; mt++)
            #pragma unroll
            for (int nt = 0; nt < 4; nt++) {
                const long long row = wm + mt * 16 + r;
                const int col = wn + nt * 8 + c2;
                *(float2*)&C[row * ldc + col]       = make_float2(acc[mt][nt][0], acc[mt][nt][1]);
                *(float2*)&C[(row + 8) * ldc + col] = make_float2(acc[mt][nt][2], acc[mt][nt][3]);
            }
    } else {
        bf16* CH = Ch + z * sC + (long long)blockIdx.y * 128 * ldc + blockIdx.x * 128;
        bf16* CL = Cl + z * sC + (long long)blockIdx.y * 128 * ldc + blockIdx.x * 128;
        #pragma unroll
        for (int mt = 0; mt < 4; mt++)
            #pragma unroll
            for (int nt = 0; nt < 4; nt++) {
                const long long row = wm + mt * 16 + r;
                const int col = wn + nt * 8 + c2;
                bf16 h0,h1,l0,l1;
                split2(acc[mt][nt][0], h0, l0); split2(acc[mt][nt][1], h1, l1);
                *(__nv_bfloat162*)&CH[row * ldc + col] = __nv_bfloat162(h0,h1);
                *(__nv_bfloat162*)&CL[row * ldc + col] = __nv_bfloat162(l0,l1);
                split2(acc[mt][nt][2], h0, l0); split2(acc[mt][nt][3], h1, l1);
                *(__nv_bfloat162*)&CH[(row+8) * ldc + col] = __nv_bfloat162(h0,h1);
                *(__nv_bfloat162*)&CL[(row+8) * ldc + col] = __nv_bfloat162(l0,l1);
            }
    }
}

// ---------------- kernel: softmax -> attn hi/lo ----------------
__global__ void softmax_kernel(const float* __restrict__ Sc)
{
    const long long row = (long long)blockIdx.y * SEQ + blockIdx.x;
    const float4* p = (const float4*)(Sc + row * SEQ);
    const int tid = threadIdx.x;                 // 0..255
    const int warp = tid >> 5, lane = tid & 31;

    const float scale = 0.044194173824159216f;   // 1/sqrt(512)
    float4 v = p[tid];
    v.x *= scale; v.y *= scale; v.z *= scale; v.w *= scale;

    __shared__ float redM[8], redS[8];

    float mx = fmaxf(fmaxf(v.x, v.y), fmaxf(v.z, v.w));
    #pragma unroll
    for (int o = 16; o > 0; o >>= 1) mx = fmaxf(mx, __shfl_xor_sync(0xFFFFFFFFu, mx, o));
    if (lane == 0) redM[warp] = mx;
    __syncthreads();
    mx = redM[0];
    #pragma unroll
    for (int i = 1; i < 8; i++) mx = fmaxf(mx, redM[i]);

    float e0 = expf(v.x - mx), e1 = expf(v.y - mx);
    float e2 = expf(v.z - mx), e3 = expf(v.w - mx);
    float sum = e0 + e1 + e2 + e3;
    #pragma unroll
    for (int o = 16; o > 0; o >>= 1) sum += __shfl_xor_sync(0xFFFFFFFFu, sum, o);
    if (lane == 0) redS[warp] = sum;
    __syncthreads();
    sum = redS[0]+redS[1]+redS[2]+redS[3]+redS[4]+redS[5]+redS[6]+redS[7];

    const float inv = 1.0f / sum;
    e0 *= inv; e1 *= inv; e2 *= inv; e3 *= inv;

    bf16 h0,h1,h2,h3,l0,l1,l2,l3;
    split2(e0,h0,l0); split2(e1,h1,l1); split2(e2,h2,l2); split2(e3,h3,l3);
    const long long base = row * SEQ + tid * 4;
    *(__nv_bfloat162*)&g_ah[base]   = __nv_bfloat162(h0,h1);
    *(__nv_bfloat162*)&g_ah[base+2] = __nv_bfloat162(h2,h3);
    *(__nv_bfloat162*)&g_al[base]   = __nv_bfloat162(l0,l1);
    *(__nv_bfloat162*)&g_al[base+2] = __nv_bfloat162(l2,l3);
}

// ---------------------------------------------------------------------------
extern "C" void kernel_launch(void* const* d_in, const int* in_sizes, int n_in,
                              void* d_out, int out_size)
{
    const int*   inp   = (const int*)  d_in[0];
    const float* wemb  = (const float*)d_in[1];
    const float* pemb  = (const float*)d_in[2];
    const float* gamma = (const float*)d_in[3];
    const float* beta  = (const float*)d_in[4];
    const float* Wk    = (const float*)d_in[5];
    const float* Wq    = (const float*)d_in[6];
    const float* Wv    = (const float*)d_in[7];
    float* out = (float*)d_out;

    bf16 *xh,*xl,*qh,*ql,*kh,*kl,*vh,*vl,*ah,*al,*wh,*wl;
    float *ps;
    cudaGetSymbolAddress((void**)&xh, g_xh); cudaGetSymbolAddress((void**)&xl, g_xl);
    cudaGetSymbolAddress((void**)&qh, g_qh); cudaGetSymbolAddress((void**)&ql, g_ql);
    cudaGetSymbolAddress((void**)&kh, g_kh); cudaGetSymbolAddress((void**)&kl, g_kl);
    cudaGetSymbolAddress((void**)&vh, g_vh); cudaGetSymbolAddress((void**)&vl, g_vl);
    cudaGetSymbolAddress((void**)&ah, g_ah); cudaGetSymbolAddress((void**)&al, g_al);
    cudaGetSymbolAddress((void**)&wh, g_wh); cudaGetSymbolAddress((void**)&wl, g_wl);
    cudaGetSymbolAddress((void**)&ps, g_s);

    const int SMEMSZ = 3 * 32768;  // 98304 B -> 2 CTAs/SM
    cudaFuncSetAttribute(gemm2<1,1>, cudaFuncAttributeMaxDynamicSharedMemorySize, SMEMSZ);
    cudaFuncSetAttribute(gemm2<0,0>, cudaFuncAttributeMaxDynamicSharedMemorySize, SMEMSZ);
    cudaFuncSetAttribute(gemm2<1,0>, cudaFuncAttributeMaxDynamicSharedMemorySize, SMEMSZ);

    // 0) split weights (slot order: q, k, v)
    split_w_kernel<<<3*DIM*DIM/256, 256>>>(Wq, Wk, Wv);

    // 1) embedding + layernorm -> xh/xl
    embed_ln_kernel<<<NTOK, 128>>>(inp, wemb, pemb, gamma, beta);

    // 2) Q/K/V projections: [32768,512] x W[512,512] (KN layout), split output
    dim3 gproj(DIM/128, NTOK/128, 1);
    gemm2<1,1><<<gproj, 256, SMEMSZ>>>(xh, xl, wh,             wl,             nullptr, qh, ql,
                                       DIM, DIM, DIM, DIM, 0, 0, 0);
    gemm2<1,1><<<gproj, 256, SMEMSZ>>>(xh, xl, wh + DIM*DIM,   wl + DIM*DIM,   nullptr, kh, kl,
                                       DIM, DIM, DIM, DIM, 0, 0, 0);
    gemm2<1,1><<<gproj, 256, SMEMSZ>>>(xh, xl, wh + 2*DIM*DIM, wl + 2*DIM*DIM, nullptr, vh, vl,
                                       DIM, DIM, DIM, DIM, 0, 0, 0);

    // 3) scores = Q @ K^T (batched, B = K matrix in natural [N][K] layout)
    dim3 gsc(SEQ/128, SEQ/128, BQ);
    gemm2<0,0><<<gsc, 256, SMEMSZ>>>(qh, ql, kh, kl, ps, nullptr, nullptr,
                                     DIM, DIM, DIM, SEQ,
                                     (long long)SEQ*DIM, (long long)SEQ*DIM,
                                     (long long)SEQ*SEQ);

    // 4) softmax -> attn hi/lo
    softmax_kernel<<<dim3(SEQ, BQ), 256>>>(ps);

    // 5) out = attn @ V (batched, V in natural [K][N] layout)
    dim3 gav(DIM/128, SEQ/128, BQ);
    gemm2<1,0><<<gav, 256, SMEMSZ>>>(ah, al, vh, vl, out, nullptr, nullptr,
                                     SEQ, SEQ, DIM, DIM,
                                     (long long)SEQ*SEQ, (long long)SEQ*DIM,
                                     (long long)SEQ*DIM);
}